// round 13
// baseline (speedup 1.0000x reference)
#include <cuda_runtime.h>
#include <math.h>
#include <stdint.h>

// Problem constants (fixed by the dataset)
#define Nn 20000
#define Ee 320000
#define Bb 128
#define Ff 128
#define Hh 256
#define EDd 16
#define Gg 16
#define Pp 2000
#define Ll 4
#define ZD (Hh + Gg)          // 272
#define K1 (2 * Hh + 1 + EDd) // 529

// ---------------- scratch (device globals; no allocation allowed) ----------
__device__ float g_h[Nn * Hh];
__device__ float g_hout[Nn * Hh];
__device__ float g_n1[Nn * Hh];
__device__ float g_agg[Nn * Hh];
__device__ float g_coord[Nn * 3];
__device__ float g_cnt[Nn];
__device__ float g_diff[Ee * 3];
__device__ float g_radial[Ee];
__device__ float g_m2[(size_t)Ee * Hh];
__device__ float g_c[Ee];
__device__ float g_z[Bb * ZD];
__device__ float g_t[Bb * Hh];
__device__ int   g_s[Bb];
__device__ int   g_e[Bb];
__device__ float g_xr[Nn * Ff];
__device__ float g_pr[Nn * Hh];
__device__ float g_pc[Nn * Hh];
__device__ float g_zb[Hh];               // zeros (zero-init)

// packed tf32 weights (mma.sync fragment order), all Ncol=256
#define SZ_K128 (128 * 256)
#define SZ_K256 (256 * 256)
#define SZ_K512 (512 * 256)
#define OFF_EMBW 0
#define OFF_PR   (OFF_EMBW + SZ_K128)
#define OFF_PC   (OFF_PR + Ll * SZ_K256)
#define OFF_EW2  (OFF_PC + Ll * SZ_K256)
#define OFF_CW1  (OFF_EW2 + Ll * SZ_K256)
#define OFF_NW1  (OFF_CW1 + Ll * SZ_K256)
#define OFF_NW2  (OFF_NW1 + Ll * SZ_K512)
#define OFF_EOW  (OFF_NW2 + Ll * SZ_K256)
#define WR_TOTAL (OFF_EOW + SZ_K256)
__device__ float g_wr[WR_TOTAL];

// dynamic smem: As 3*128*20 + Bs 3*2048 floats (+ combine weights for AMODE 3)
#define GT_AS_FLOATS (3 * 128 * 20)
#define GT_BASE_FLOATS (GT_AS_FLOATS + 3 * 2048)
#define GT_SMEM_BYTES (GT_BASE_FLOATS * 4)                    // 55296 B
#define GT_EX_FLOATS (EDd * 256 + 256 + 256)                  // wea + wrad + b1 = 4608
#define GT_SMEM_FUSED ((GT_BASE_FLOATS + GT_EX_FLOATS) * 4)   // 73728 B

__device__ __forceinline__ float f2tf32_f(float x) {
    uint32_t r;
    asm("cvt.rna.tf32.f32 %0, %1;" : "=r"(r) : "f"(x));
    return __uint_as_float(r);
}

__device__ __forceinline__ void mma_tf32(float* d, const uint32_t* a, const uint32_t* b) {
    asm volatile(
        "mma.sync.aligned.m16n8k8.row.col.f32.tf32.tf32.f32 "
        "{%0,%1,%2,%3}, {%4,%5,%6,%7}, {%8,%9}, {%0,%1,%2,%3};"
        : "+f"(d[0]), "+f"(d[1]), "+f"(d[2]), "+f"(d[3])
        : "r"(a[0]), "r"(a[1]), "r"(a[2]), "r"(a[3]), "r"(b[0]), "r"(b[1]));
}

__device__ __forceinline__ void cpa16(uint32_t saddr, const void* gptr) {
    asm volatile("cp.async.cg.shared.global [%0], [%1], 16;" :: "r"(saddr), "l"(gptr));
}

__device__ __forceinline__ void red_add_v2(float* gptr, float a, float b) {
    asm volatile("red.global.add.v2.f32 [%0], {%1, %2};"
                 :: "l"(gptr), "f"(a), "f"(b) : "memory");
}

__device__ __forceinline__ float silu_f(float v) { return v / (1.f + expf(-v)); }

__global__ void round_tf32_kernel(const float* __restrict__ in, float* __restrict__ out, int n)
{
    int i = blockIdx.x * blockDim.x + threadIdx.x;
    if (i < n) out[i] = f2tf32_f(in[i]);
}

__global__ void round_inplace_kernel(float* __restrict__ p, int n)
{
    int i = blockIdx.x * blockDim.x + threadIdx.x;
    if (i < n) p[i] = f2tf32_f(p[i]);
}

// pack W[K x 256] into fragment order [jt2][nch][ks2][nfp8][lane32][q4]
__global__ void pack_w_kernel(const float* __restrict__ src, float* __restrict__ dst,
                              int nch, int cb, long srcStride, long dstStride)
{
    int l = blockIdx.y;
    src += (size_t)l * srcStride;
    dst += (size_t)l * dstStride;
    int i = blockIdx.x * blockDim.x + threadIdx.x;
    int total = 2 * nch * 2048;
    if (i >= total) return;
    int q    = i & 3;
    int lane = (i >> 2) & 31;
    int nfp  = (i >> 7) & 7;
    int ks   = (i >> 10) & 1;
    int ch   = (i >> 11) & (nch - 1);
    int jt   = i >> (11 + cb);
    int n = jt * 128 + nfp * 16 + ((q >> 1) << 3) + (lane >> 2);
    int k = ch * 16 + ks * 8 + (lane & 3) + ((q & 1) << 2);
    dst[i] = f2tf32_f(src[(size_t)k * 256 + n]);
}

// ---------------- tf32 tensor-core GEMM: 256 thr, grid (2, M/128),
// 3-stage cp.async, ONE __syncthreads per K-chunk (CUTLASS multistage order).
// AMODE 0: A row-major ; 2: node concat [h | agg]
// AMODE 3: A computed in-loader: m1[e,k] = rnd(silu(pre_r[row,k]+pre_c[col,k]
//          + rad*wrad[k] + ea@wea[:,k] + b1[k]))    (fused edge combine)
// EPI 0: C=v ; 1: C=silu(v) ; 2: C+=v
// EPI 3: no C write; cbuf[i] += sum_j silu(v_ij)*wc2[j]   (atomic)
// EPI 4: C=rnd(silu(v)) AND agg[row[i]] += same          (red.v2)
// RND 1: round stored value to tf32.
template <int AMODE, int EPI, int RND>
__global__ __launch_bounds__(256, 2)
void gemm_tc(const float* __restrict__ A, const float* __restrict__ Bp,
             const float* __restrict__ bias, float* __restrict__ C,
             int M, int K,
             const int* __restrict__ rowIdx, const int* __restrict__ colIdx,
             const float* __restrict__ hbuf, const float* __restrict__ aggbuf,
             const float* __restrict__ radial, const float* __restrict__ eattr,
             const float* __restrict__ weap, const float* __restrict__ wradp,
             const float* __restrict__ b1p,
             const float* __restrict__ wc2, float* __restrict__ cbuf,
             float* __restrict__ aggout)
{
    extern __shared__ float smg[];
    float* AsF = smg;                       // [3][128][20]
    float* BsF = smg + GT_AS_FLOATS;        // [3][2048]
    float* EX  = smg + GT_BASE_FLOATS;      // AMODE3: wea[16][256], wrad, b1

    const int tid  = threadIdx.x;
    const int lane = tid & 31;
    const int wid  = tid >> 5;
    const int wm   = (wid >> 1) * 32;
    const int wn   = (wid & 1) * 64;
    const int g    = lane >> 2;
    const int c    = lane & 3;

    const int i0 = blockIdx.y * 128;
    const int j0 = blockIdx.x * 128;
    const int nch = K >> 4;

    const int arow  = tid >> 1;
    const int acol8 = (tid & 1) * 8;
    const int gi_a  = i0 + arow;
    const bool aok  = gi_a < M;

    const int lm_row = ((lane >> 3) & 1) * 8 + (lane & 7);
    const int lm_col = ((lane >> 4) & 1) * 4;

    const float* BpT = Bp + (size_t)blockIdx.x * nch * 2048;

    // AMODE 3 per-thread edge state
    int rA = 0, cA = 0;
    float radE = 0.f, eaR[EDd];
    if (AMODE == 3) {
        for (int t = tid; t < EDd * 256; t += 256) EX[t] = weap[t];
        EX[EDd * 256 + tid] = wradp[tid];
        EX[EDd * 256 + 256 + tid] = b1p[tid];
        rA = __ldg(&rowIdx[gi_a]);
        cA = __ldg(&colIdx[gi_a]);
        radE = __ldg(&radial[gi_a]);
#pragma unroll
        for (int i4 = 0; i4 < 4; i4++) {
            float4 v = *(const float4*)&eattr[(size_t)gi_a * EDd + i4 * 4];
            eaR[i4 * 4 + 0] = v.x; eaR[i4 * 4 + 1] = v.y;
            eaR[i4 * 4 + 2] = v.z; eaR[i4 * 4 + 3] = v.w;
        }
        __syncthreads();
    }

    auto load_stage = [&](int st, int ch) {
        const int k0 = ch * 16;
        float* asd = AsF + st * 2560 + arow * 20 + acol8;
        if (AMODE == 3) {
            const int kb = k0 + acol8;
            float4 a0 = *(const float4*)&hbuf[(size_t)rA * Hh + kb];
            float4 a1 = *(const float4*)&hbuf[(size_t)rA * Hh + kb + 4];
            float4 b0 = *(const float4*)&aggbuf[(size_t)cA * Hh + kb];
            float4 b1v = *(const float4*)&aggbuf[(size_t)cA * Hh + kb + 4];
            float4 w0 = *(const float4*)&EX[EDd * 256 + kb];
            float4 w1 = *(const float4*)&EX[EDd * 256 + kb + 4];
            float4 c0 = *(const float4*)&EX[EDd * 256 + 256 + kb];
            float4 c1 = *(const float4*)&EX[EDd * 256 + 256 + kb + 4];
            float v[8];
            v[0] = a0.x + b0.x + radE * w0.x + c0.x;
            v[1] = a0.y + b0.y + radE * w0.y + c0.y;
            v[2] = a0.z + b0.z + radE * w0.z + c0.z;
            v[3] = a0.w + b0.w + radE * w0.w + c0.w;
            v[4] = a1.x + b1v.x + radE * w1.x + c1.x;
            v[5] = a1.y + b1v.y + radE * w1.y + c1.y;
            v[6] = a1.z + b1v.z + radE * w1.z + c1.z;
            v[7] = a1.w + b1v.w + radE * w1.w + c1.w;
#pragma unroll
            for (int j = 0; j < EDd; j++) {
                float4 e0 = *(const float4*)&EX[j * 256 + kb];
                float4 e1 = *(const float4*)&EX[j * 256 + kb + 4];
                float e = eaR[j];
                v[0] = fmaf(e, e0.x, v[0]); v[1] = fmaf(e, e0.y, v[1]);
                v[2] = fmaf(e, e0.z, v[2]); v[3] = fmaf(e, e0.w, v[3]);
                v[4] = fmaf(e, e1.x, v[4]); v[5] = fmaf(e, e1.y, v[5]);
                v[6] = fmaf(e, e1.z, v[6]); v[7] = fmaf(e, e1.w, v[7]);
            }
#pragma unroll
            for (int jj = 0; jj < 8; jj++) asd[jj] = f2tf32_f(silu_f(v[jj]));
        } else if (!aok) {
#pragma unroll
            for (int jj = 0; jj < 8; jj++) asd[jj] = 0.f;
        } else {
            const float* base;
            if (AMODE == 0) base = A + (size_t)gi_a * K + k0;
            else            base = (k0 < Hh) ? hbuf + (size_t)gi_a * Hh + k0
                                             : aggbuf + (size_t)gi_a * Hh + (k0 - Hh);
            uint32_t s = (uint32_t)__cvta_generic_to_shared(asd);
            cpa16(s, base + acol8);
            cpa16(s + 16, base + acol8 + 4);
        }
        const float* src = BpT + (size_t)ch * 2048 + tid * 4;
        uint32_t s = (uint32_t)__cvta_generic_to_shared(&BsF[st * 2048 + tid * 4]);
        cpa16(s, src);
        cpa16(s + 4096, src + 1024);
    };

    float acc[2][8][4];
#pragma unroll
    for (int a = 0; a < 2; a++)
#pragma unroll
        for (int b = 0; b < 8; b++)
#pragma unroll
            for (int q = 0; q < 4; q++) acc[a][b][q] = 0.f;

    load_stage(0, 0);
    asm volatile("cp.async.commit_group;");
    if (nch > 1) {
        load_stage(1, 1);
        asm volatile("cp.async.commit_group;");
    }

    for (int ch = 0; ch < nch; ch++) {
        const int st = ch % 3;
        const bool more = (ch + 2 < nch);
        if (more) asm volatile("cp.async.wait_group 1;");
        else      asm volatile("cp.async.wait_group 0;");
        __syncthreads();
        if (more) {
            load_stage((ch + 2) % 3, ch + 2);
            asm volatile("cp.async.commit_group;");
        }

#pragma unroll
        for (int ks = 0; ks < 2; ks++) {
            uint32_t af[2][4];
#pragma unroll
            for (int mf = 0; mf < 2; mf++) {
                uint32_t addr = (uint32_t)__cvta_generic_to_shared(
                    &AsF[st * 2560 + (wm + mf * 16 + lm_row) * 20 + ks * 8 + lm_col]);
                asm volatile(
                    "ldmatrix.sync.aligned.m8n8.x4.shared.b16 {%0,%1,%2,%3}, [%4];"
                    : "=r"(af[mf][0]), "=r"(af[mf][1]), "=r"(af[mf][2]), "=r"(af[mf][3])
                    : "r"(addr));
            }
#pragma unroll
            for (int nfp = 0; nfp < 4; nfp++) {
                float4 bv = *(const float4*)&BsF[st * 2048 +
                                                 ((ks * 8 + (wn >> 4) + nfp) * 32 + lane) * 4];
                uint32_t b0[2] = {__float_as_uint(bv.x), __float_as_uint(bv.y)};
                uint32_t b1[2] = {__float_as_uint(bv.z), __float_as_uint(bv.w)};
#pragma unroll
                for (int mf = 0; mf < 2; mf++) {
                    mma_tf32(acc[mf][2 * nfp + 0], af[mf], b0);
                    mma_tf32(acc[mf][2 * nfp + 1], af[mf], b1);
                }
            }
        }
    }

    if (EPI == 3) {
        float rsum[2][2] = {{0.f, 0.f}, {0.f, 0.f}};
#pragma unroll
        for (int mf = 0; mf < 2; mf++)
#pragma unroll
            for (int nf = 0; nf < 8; nf++)
#pragma unroll
                for (int rr = 0; rr < 2; rr++)
#pragma unroll
                    for (int q = 0; q < 2; q++) {
                        int oj = j0 + wn + nf * 8 + 2 * c + q;
                        float v = silu_f(acc[mf][nf][rr * 2 + q] + bias[oj]);
                        rsum[mf][rr] += v * wc2[oj];
                    }
#pragma unroll
        for (int mf = 0; mf < 2; mf++)
#pragma unroll
            for (int rr = 0; rr < 2; rr++) {
                float s = rsum[mf][rr];
                s += __shfl_xor_sync(0xffffffffu, s, 1);
                s += __shfl_xor_sync(0xffffffffu, s, 2);
                if (c == 0) {
                    int oi = i0 + wm + mf * 16 + g + rr * 8;
                    if (oi < M) atomicAdd(&cbuf[oi], s);
                }
            }
        return;
    }

#pragma unroll
    for (int mf = 0; mf < 2; mf++) {
#pragma unroll
        for (int rr = 0; rr < 2; rr++) {
            int oi = i0 + wm + mf * 16 + g + rr * 8;
            if (oi >= M) continue;
            int rE = 0;
            if (EPI == 4) rE = __ldg(&rowIdx[oi]);
#pragma unroll
            for (int nf = 0; nf < 8; nf++) {
                int oj0 = j0 + wn + nf * 8 + 2 * c;
                float vv[2];
#pragma unroll
                for (int q = 0; q < 2; q++) {
                    int oj = oj0 + q;
                    float v = acc[mf][nf][rr * 2 + q] + bias[oj];
                    if (EPI == 1 || EPI == 4) v = silu_f(v);
                    if (EPI == 2) v += C[(size_t)oi * Hh + oj];
                    if (RND) v = f2tf32_f(v);
                    C[(size_t)oi * Hh + oj] = v;
                    vv[q] = v;
                }
                if (EPI == 4) red_add_v2(&aggout[(size_t)rE * Hh + oj0], vv[0], vv[1]);
            }
        }
    }
}

// ---------------- SIMT SGEMM (small tails only) ----------------------------
template <int EPI>
__global__ void gemm_k(const float* __restrict__ A, const float* __restrict__ Bw,
                       const float* __restrict__ bias, float* __restrict__ C,
                       int M, int K, int Ncol)
{
    __shared__ float As[16][64];
    __shared__ float Bs[16][64];
    const int tid = threadIdx.x;
    const int tx = tid & 15, ty = tid >> 4;
    const int i0 = blockIdx.y * 64, j0 = blockIdx.x * 64;
    const int a_row = tid >> 2, a_k = (tid & 3) * 4;
    const int b_k = tid >> 4, b_j = (tid & 15) * 4;
    float acc[4][4] = {};
    const int gi = i0 + a_row;
    for (int k0 = 0; k0 < K; k0 += 16) {
#pragma unroll
        for (int q = 0; q < 4; q++) {
            int gk = k0 + a_k + q;
            As[a_k + q][a_row] = (gi < M && gk < K) ? A[(size_t)gi * K + gk] : 0.f;
        }
        int gk = k0 + b_k;
#pragma unroll
        for (int q = 0; q < 4; q++) {
            int gj = j0 + b_j + q;
            Bs[b_k][b_j + q] = (gk < K && gj < Ncol) ? Bw[(size_t)gk * Ncol + gj] : 0.f;
        }
        __syncthreads();
#pragma unroll
        for (int kk = 0; kk < 16; kk++) {
            float4 ra = *(const float4*)&As[kk][ty * 4];
            float4 rb = *(const float4*)&Bs[kk][tx * 4];
            float av[4] = {ra.x, ra.y, ra.z, ra.w};
            float bv[4] = {rb.x, rb.y, rb.z, rb.w};
#pragma unroll
            for (int m = 0; m < 4; m++)
#pragma unroll
                for (int n = 0; n < 4; n++) acc[m][n] += av[m] * bv[n];
        }
        __syncthreads();
    }
#pragma unroll
    for (int m = 0; m < 4; m++) {
        int oi = i0 + ty * 4 + m;
        if (oi >= M) continue;
#pragma unroll
        for (int n = 0; n < 4; n++) {
            int oj = j0 + tx * 4 + n;
            if (oj >= Ncol) continue;
            float v = acc[m][n] + bias[oj];
            if (EPI == 1) v = silu_f(v);
            if (EPI == 2) C[(size_t)oi * Ncol + oj] += v;
            else          C[(size_t)oi * Ncol + oj] = v;
        }
    }
}

// ---------------- small helper kernels -------------------------------------
__global__ void init_kernel(const float* __restrict__ pos, float* __restrict__ coord,
                            float* __restrict__ cnt)
{
    int i = blockIdx.x * blockDim.x + threadIdx.x;
    if (i >= Nn) return;
    cnt[i] = 0.f;
    coord[3 * i + 0] = pos[3 * i + 0];
    coord[3 * i + 1] = pos[3 * i + 1];
    coord[3 * i + 2] = pos[3 * i + 2];
}

__global__ void count_kernel(const int* __restrict__ row, float* __restrict__ cnt)
{
    int e = blockIdx.x * blockDim.x + threadIdx.x;
    if (e >= Ee) return;
    atomicAdd(&cnt[row[e]], 1.f);
}

__global__ void edge_geom_kernel(const float* __restrict__ coord,
                                 const int* __restrict__ row, const int* __restrict__ col,
                                 float* __restrict__ diff, float* __restrict__ radial)
{
    int e = blockIdx.x * blockDim.x + threadIdx.x;
    if (e >= Ee) return;
    int r = row[e], c = col[e];
    float dx = coord[3 * r + 0] - coord[3 * c + 0];
    float dy = coord[3 * r + 1] - coord[3 * c + 1];
    float dz = coord[3 * r + 2] - coord[3 * c + 2];
    diff[3 * e + 0] = dx; diff[3 * e + 1] = dy; diff[3 * e + 2] = dz;
    radial[e] = dx * dx + dy * dy + dz * dz;
}

__global__ void zero2_kernel(float* __restrict__ a, int na, float* __restrict__ b, int nb)
{
    int i = blockIdx.x * blockDim.x + threadIdx.x;
    if (i < na) a[i] = 0.f;
    else if (i < na + nb) b[i - na] = 0.f;
}

__global__ void coord_update_kernel(const float* __restrict__ diff, const float* __restrict__ cbuf,
                                    const int* __restrict__ row, const float* __restrict__ cnt,
                                    float* __restrict__ coord)
{
    int e = blockIdx.x * blockDim.x + threadIdx.x;
    if (e >= Ee) return;
    int r = row[e];
    float s = cbuf[e] / fmaxf(cnt[r], 1.f);
    atomicAdd(&coord[3 * r + 0], diff[3 * e + 0] * s);
    atomicAdd(&coord[3 * r + 1], diff[3 * e + 1] * s);
    atomicAdd(&coord[3 * r + 2], diff[3 * e + 2] * s);
}

__global__ void bounds_kernel(const int* __restrict__ batch, int* __restrict__ s,
                              int* __restrict__ e)
{
    int i = blockIdx.x * blockDim.x + threadIdx.x;
    if (i >= Nn) return;
    int b = batch[i];
    if (i == 0) s[b] = 0;
    else {
        int pb = batch[i - 1];
        if (pb != b) { s[b] = i; e[pb] = i; }
    }
    if (i == Nn - 1) e[b] = Nn;
}

__global__ void pool_kernel(const float* __restrict__ hout, const int* __restrict__ s,
                            const int* __restrict__ e, const float* __restrict__ frag,
                            const float* __restrict__ addf, float* __restrict__ z)
{
    int b = blockIdx.x;
    int j = threadIdx.x;
    float m = -INFINITY;
    int n0 = s[b], n1 = e[b];
    for (int n = n0; n < n1; n++) m = fmaxf(m, hout[(size_t)n * Hh + j]);
    z[b * ZD + j] = m;
    if (j < 8)       z[b * ZD + Hh + j] = frag[b * 8 + j];
    else if (j < 16) z[b * ZD + Hh + j] = addf[b * 8 + (j - 8)];
}

// ---------------- launch ----------------------------------------------------
extern "C" void kernel_launch(void* const* d_in, const int* in_sizes, int n_in,
                              void* d_out, int out_size)
{
    const float* x        = (const float*)d_in[0];
    const float* pos      = (const float*)d_in[1];
    const float* eattr    = (const float*)d_in[2];
    const float* frag     = (const float*)d_in[3];
    const float* addf     = (const float*)d_in[4];
    const int*   eidx     = (const int*)d_in[5];
    const int*   batch    = (const int*)d_in[6];
    const float* emb_in_w = (const float*)d_in[7];
    const float* emb_in_b = (const float*)d_in[8];
    const float* edge_w1  = (const float*)d_in[9];
    const float* edge_b1  = (const float*)d_in[10];
    const float* edge_w2  = (const float*)d_in[11];
    const float* edge_b2  = (const float*)d_in[12];
    const float* node_w1  = (const float*)d_in[13];
    const float* node_b1  = (const float*)d_in[14];
    const float* node_w2  = (const float*)d_in[15];
    const float* node_b2  = (const float*)d_in[16];
    const float* coord_w1 = (const float*)d_in[17];
    const float* coord_b1 = (const float*)d_in[18];
    const float* coord_w2 = (const float*)d_in[19];
    const float* emb_out_w= (const float*)d_in[20];
    const float* emb_out_b= (const float*)d_in[21];
    const float* res_w1   = (const float*)d_in[22];
    const float* res_b1   = (const float*)d_in[23];
    const float* res_w2   = (const float*)d_in[24];
    const float* res_b2   = (const float*)d_in[25];
    const float* head_w   = (const float*)d_in[26];
    const float* head_b   = (const float*)d_in[27];
    float* out = (float*)d_out;
    const int* row = eidx;
    const int* col = eidx + Ee;

    float *h, *hout, *n1, *agg, *coord, *cnt, *diff, *radial, *m2, *cbuf, *z, *tbuf;
    float *xr, *wr, *pr, *pc, *zb;
    int *sb, *eb;
    cudaGetSymbolAddress((void**)&h, g_h);
    cudaGetSymbolAddress((void**)&hout, g_hout);
    cudaGetSymbolAddress((void**)&n1, g_n1);
    cudaGetSymbolAddress((void**)&agg, g_agg);
    cudaGetSymbolAddress((void**)&coord, g_coord);
    cudaGetSymbolAddress((void**)&cnt, g_cnt);
    cudaGetSymbolAddress((void**)&diff, g_diff);
    cudaGetSymbolAddress((void**)&radial, g_radial);
    cudaGetSymbolAddress((void**)&m2, g_m2);
    cudaGetSymbolAddress((void**)&cbuf, g_c);
    cudaGetSymbolAddress((void**)&z, g_z);
    cudaGetSymbolAddress((void**)&tbuf, g_t);
    cudaGetSymbolAddress((void**)&sb, g_s);
    cudaGetSymbolAddress((void**)&eb, g_e);
    cudaGetSymbolAddress((void**)&xr, g_xr);
    cudaGetSymbolAddress((void**)&wr, g_wr);
    cudaGetSymbolAddress((void**)&pr, g_pr);
    cudaGetSymbolAddress((void**)&pc, g_pc);
    cudaGetSymbolAddress((void**)&zb, g_zb);

    cudaFuncSetAttribute(gemm_tc<0, 0, 1>, cudaFuncAttributeMaxDynamicSharedMemorySize, GT_SMEM_BYTES);
    cudaFuncSetAttribute(gemm_tc<0, 0, 0>, cudaFuncAttributeMaxDynamicSharedMemorySize, GT_SMEM_BYTES);
    cudaFuncSetAttribute(gemm_tc<3, 4, 1>, cudaFuncAttributeMaxDynamicSharedMemorySize, GT_SMEM_FUSED);
    cudaFuncSetAttribute(gemm_tc<0, 3, 0>, cudaFuncAttributeMaxDynamicSharedMemorySize, GT_SMEM_BYTES);
    cudaFuncSetAttribute(gemm_tc<2, 1, 1>, cudaFuncAttributeMaxDynamicSharedMemorySize, GT_SMEM_BYTES);
    cudaFuncSetAttribute(gemm_tc<0, 2, 1>, cudaFuncAttributeMaxDynamicSharedMemorySize, GT_SMEM_BYTES);

    const dim3 T(256), T256(256);
    const dim3 gE(2, Ee / 128);               // 2 x 2500
    const dim3 gN(2, (Nn + 127) / 128);       // 2 x 157

    // ---- pack weights into tf32 fragment order ----
    pack_w_kernel<<<dim3((SZ_K128 + 255) / 256, 1), T>>>(emb_in_w, wr + OFF_EMBW, 8, 3, 0, 0);
    pack_w_kernel<<<dim3((SZ_K256 + 255) / 256, Ll), T>>>(edge_w1, wr + OFF_PR, 16, 4,
                                                          (long)K1 * Hh, SZ_K256);
    pack_w_kernel<<<dim3((SZ_K256 + 255) / 256, Ll), T>>>(edge_w1 + (size_t)Hh * Hh, wr + OFF_PC, 16, 4,
                                                          (long)K1 * Hh, SZ_K256);
    pack_w_kernel<<<dim3((SZ_K256 + 255) / 256, Ll), T>>>(edge_w2, wr + OFF_EW2, 16, 4,
                                                          (long)Hh * Hh, SZ_K256);
    pack_w_kernel<<<dim3((SZ_K256 + 255) / 256, Ll), T>>>(coord_w1, wr + OFF_CW1, 16, 4,
                                                          (long)Hh * Hh, SZ_K256);
    pack_w_kernel<<<dim3((SZ_K512 + 255) / 256, Ll), T>>>(node_w1, wr + OFF_NW1, 32, 5,
                                                          (long)2 * Hh * Hh, SZ_K512);
    pack_w_kernel<<<dim3((SZ_K256 + 255) / 256, Ll), T>>>(node_w2, wr + OFF_NW2, 16, 4,
                                                          (long)Hh * Hh, SZ_K256);
    pack_w_kernel<<<dim3((SZ_K256 + 255) / 256, 1), T>>>(emb_out_w, wr + OFF_EOW, 16, 4, 0, 0);
    round_tf32_kernel<<<(Nn * Ff + 255) / 256, T>>>(x, xr, Nn * Ff);

    init_kernel<<<(Nn + 255) / 256, T>>>(pos, coord, cnt);
    count_kernel<<<(Ee + 255) / 256, T>>>(row, cnt);

    // h = x @ emb_in_w + b   (rounded)
    gemm_tc<0, 0, 1><<<gN, T256, GT_SMEM_BYTES>>>(xr, wr + OFF_EMBW, emb_in_b, h, Nn, Ff,
        nullptr, nullptr, nullptr, nullptr, nullptr, nullptr, nullptr, nullptr, nullptr,
        nullptr, nullptr, nullptr);

    for (int l = 0; l < Ll; l++) {
        edge_geom_kernel<<<(Ee + 255) / 256, T>>>(coord, row, col, diff, radial);
        // node pre-projections (no bias; consumed in fp32)
        gemm_tc<0, 0, 0><<<gN, T256, GT_SMEM_BYTES>>>(h, wr + OFF_PR + (size_t)l * SZ_K256, zb, pr,
            Nn, Hh, nullptr, nullptr, nullptr, nullptr, nullptr, nullptr, nullptr, nullptr,
            nullptr, nullptr, nullptr, nullptr);
        gemm_tc<0, 0, 0><<<gN, T256, GT_SMEM_BYTES>>>(h, wr + OFF_PC + (size_t)l * SZ_K256, zb, pc,
            Nn, Hh, nullptr, nullptr, nullptr, nullptr, nullptr, nullptr, nullptr, nullptr,
            nullptr, nullptr, nullptr, nullptr);
        zero2_kernel<<<(Nn * Hh + Ee + 255) / 256, T>>>(agg, Nn * Hh, cbuf, Ee);
        // m2 = silu(m1 @ W2 + b2) with m1 computed in-loader (fused combine);
        // fused agg scatter (red.v2)
        gemm_tc<3, 4, 1><<<gE, T256, GT_SMEM_FUSED>>>(nullptr, wr + OFF_EW2 + (size_t)l * SZ_K256,
            edge_b2 + l * Hh, m2, Ee, Hh,
            row, col, pr, pc, radial, eattr,
            edge_w1 + ((size_t)l * K1 + 2 * Hh + 1) * Hh,    // wea rows 513..528
            edge_w1 + ((size_t)l * K1 + 2 * Hh) * Hh,        // wrad row 512
            edge_b1 + l * Hh,
            nullptr, nullptr, agg);
        // c[e] = silu(m2 @ Wc1 + bc1) @ wc2
        gemm_tc<0, 3, 0><<<gE, T256, GT_SMEM_BYTES>>>(m2, wr + OFF_CW1 + (size_t)l * SZ_K256,
            coord_b1 + l * Hh, nullptr, Ee, Hh,
            nullptr, nullptr, nullptr, nullptr, nullptr, nullptr, nullptr, nullptr, nullptr,
            coord_w2 + l * Hh, cbuf, nullptr);
        coord_update_kernel<<<(Ee + 255) / 256, T>>>(diff, cbuf, row, cnt, coord);
        round_inplace_kernel<<<(Nn * Hh + 255) / 256, T>>>(agg, Nn * Hh);
        // n1 = silu(concat(h,agg) @ nW1 + nb1)
        gemm_tc<2, 1, 1><<<gN, T256, GT_SMEM_BYTES>>>(nullptr, wr + OFF_NW1 + (size_t)l * SZ_K512,
            node_b1 + l * Hh, n1, Nn, 2 * Hh,
            nullptr, nullptr, h, agg, nullptr, nullptr, nullptr, nullptr, nullptr,
            nullptr, nullptr, nullptr);
        // h += n1 @ nW2 + nb2
        gemm_tc<0, 2, 1><<<gN, T256, GT_SMEM_BYTES>>>(n1, wr + OFF_NW2 + (size_t)l * SZ_K256,
            node_b2 + l * Hh, h, Nn, Hh,
            nullptr, nullptr, nullptr, nullptr, nullptr, nullptr, nullptr, nullptr, nullptr,
            nullptr, nullptr, nullptr);
    }

    // hout = h @ emb_out_w + b
    gemm_tc<0, 0, 0><<<gN, T256, GT_SMEM_BYTES>>>(h, wr + OFF_EOW, emb_out_b, hout, Nn, Hh,
        nullptr, nullptr, nullptr, nullptr, nullptr, nullptr, nullptr, nullptr, nullptr,
        nullptr, nullptr, nullptr);

    bounds_kernel<<<(Nn + 255) / 256, T>>>(batch, sb, eb);
    pool_kernel<<<Bb, T>>>(hout, sb, eb, frag, addf, z);

    gemm_k<1><<<dim3(4, 2), T>>>(z, res_w1, res_b1, tbuf, Bb, ZD, Hh);
    gemm_k<2><<<dim3((ZD + 63) / 64, 2), T>>>(tbuf, res_w2, res_b2, z, Bb, Hh, ZD);
    gemm_k<0><<<dim3((Pp + 63) / 64, 2), T>>>(z, head_w, head_b, out, Bb, ZD, Pp);
}

// round 14
// speedup vs baseline: 1.0769x; 1.0769x over previous
#include <cuda_runtime.h>
#include <math.h>
#include <stdint.h>

// Problem constants (fixed by the dataset)
#define Nn 20000
#define Ee 320000
#define Bb 128
#define Ff 128
#define Hh 256
#define EDd 16
#define Gg 16
#define Pp 2000
#define Ll 4
#define ZD (Hh + Gg)          // 272
#define K1 (2 * Hh + 1 + EDd) // 529

// ---------------- scratch (device globals; no allocation allowed) ----------
__device__ float g_h[Nn * Hh];
__device__ float g_hout[Nn * Hh];
__device__ float g_n1[Nn * Hh];
__device__ float g_agg[Nn * Hh];
__device__ float g_coord[Nn * 3];
__device__ float g_cnt[Nn];
__device__ float g_diff[Ee * 3];
__device__ float g_radial[Ee];
__device__ float g_m1[(size_t)Ee * Hh];
__device__ float g_m2[(size_t)Ee * Hh];
__device__ float g_c[Ee];
__device__ float g_z[Bb * ZD];
__device__ float g_t[Bb * Hh];
__device__ int   g_s[Bb];
__device__ int   g_e[Bb];
__device__ float g_xr[Nn * Ff];
__device__ float g_pr[Nn * Hh];
__device__ float g_pc[Nn * Hh];
__device__ float g_zb[Hh];               // zeros (zero-init)

// packed tf32 weights (fragment order), all Ncol=256
#define SZ_K128 (128 * 256)
#define SZ_K256 (256 * 256)
#define SZ_K512 (512 * 256)
#define OFF_EMBW 0
#define OFF_PR   (OFF_EMBW + SZ_K128)
#define OFF_PC   (OFF_PR + Ll * SZ_K256)
#define OFF_EW2  (OFF_PC + Ll * SZ_K256)
#define OFF_CW1  (OFF_EW2 + Ll * SZ_K256)
#define OFF_NW1  (OFF_CW1 + Ll * SZ_K256)
#define OFF_NW2  (OFF_NW1 + Ll * SZ_K512)
#define OFF_EOW  (OFF_NW2 + Ll * SZ_K256)
#define WR_TOTAL (OFF_EOW + SZ_K256)
__device__ float g_wr[WR_TOTAL];

// dynamic smem for gemm_tc (3-stage): As 3*128*20 + Bs 3*2048 floats
#define GT_AS_FLOATS (3 * 128 * 20)
#define GT_SMEM_BYTES ((GT_AS_FLOATS + 3 * 2048) * 4)   // 55296 B

__device__ __forceinline__ float f2tf32_f(float x) {
    uint32_t r;
    asm("cvt.rna.tf32.f32 %0, %1;" : "=r"(r) : "f"(x));
    return __uint_as_float(r);
}

__device__ __forceinline__ void mma_tf32(float* d, const uint32_t* a, const uint32_t* b) {
    asm volatile(
        "mma.sync.aligned.m16n8k8.row.col.f32.tf32.tf32.f32 "
        "{%0,%1,%2,%3}, {%4,%5,%6,%7}, {%8,%9}, {%0,%1,%2,%3};"
        : "+f"(d[0]), "+f"(d[1]), "+f"(d[2]), "+f"(d[3])
        : "r"(a[0]), "r"(a[1]), "r"(a[2]), "r"(a[3]), "r"(b[0]), "r"(b[1]));
}

__device__ __forceinline__ void cpa16(uint32_t saddr, const void* gptr) {
    asm volatile("cp.async.cg.shared.global [%0], [%1], 16;" :: "r"(saddr), "l"(gptr));
}

// vectorized fire-and-forget reduction (sm_90+)
__device__ __forceinline__ void red_add_v2(float* gptr, float a, float b) {
    asm volatile("red.global.add.v2.f32 [%0], {%1, %2};"
                 :: "l"(gptr), "f"(a), "f"(b) : "memory");
}

__device__ __forceinline__ float silu_f(float v) { return v / (1.f + expf(-v)); }

__global__ void round_tf32_kernel(const float* __restrict__ in, float* __restrict__ out, int n)
{
    int i = blockIdx.x * blockDim.x + threadIdx.x;
    if (i < n) out[i] = f2tf32_f(in[i]);
}

__global__ void round_inplace_kernel(float* __restrict__ p, int n)
{
    int i = blockIdx.x * blockDim.x + threadIdx.x;
    if (i < n) p[i] = f2tf32_f(p[i]);
}

// pack W[K x 256] into fragment order [jt2][nch][ks2][nfp8][lane32][q4]
__global__ void pack_w_kernel(const float* __restrict__ src, float* __restrict__ dst,
                              int nch, int cb, long srcStride, long dstStride)
{
    int l = blockIdx.y;
    src += (size_t)l * srcStride;
    dst += (size_t)l * dstStride;
    int i = blockIdx.x * blockDim.x + threadIdx.x;
    int total = 2 * nch * 2048;
    if (i >= total) return;
    int q    = i & 3;
    int lane = (i >> 2) & 31;
    int nfp  = (i >> 7) & 7;
    int ks   = (i >> 10) & 1;
    int ch   = (i >> 11) & (nch - 1);
    int jt   = i >> (11 + cb);
    int n = jt * 128 + nfp * 16 + ((q >> 1) << 3) + (lane >> 2);
    int k = ch * 16 + ks * 8 + (lane & 3) + ((q & 1) << 2);
    dst[i] = f2tf32_f(src[(size_t)k * 256 + n]);
}

// ---------------- tf32 tensor-core GEMM: 256 thr, grid (2, M/128),
// 3-stage cp.async, ONE __syncthreads per K-chunk (CUTLASS multistage order).
// AMODE 0: A row-major ; 2: node concat [h | agg]
// EPI 0: C=v ; 1: C=silu(v) ; 2: C+=v
// EPI 3: no C write; cbuf[i] += sum_j silu(v_ij)*wc2[j]   (atomic)
// EPI 4: C=silu(v) AND agg[row[i]] += silu(v)             (red.v2)
// RND 1: round stored value to tf32.
template <int AMODE, int EPI, int RND>
__global__ __launch_bounds__(256, 2)
void gemm_tc(const float* __restrict__ A, const float* __restrict__ Bp,
             const float* __restrict__ bias, float* __restrict__ C,
             int M, int K,
             const int* __restrict__ rowIdx,
             const float* __restrict__ hbuf, const float* __restrict__ aggbuf,
             const float* __restrict__ wc2, float* __restrict__ cbuf,
             float* __restrict__ aggout)
{
    extern __shared__ float smg[];
    float* AsF = smg;                       // [3][128][20]
    float* BsF = smg + GT_AS_FLOATS;        // [3][2048]

    const int tid  = threadIdx.x;
    const int lane = tid & 31;
    const int wid  = tid >> 5;
    const int wm   = (wid >> 1) * 32;
    const int wn   = (wid & 1) * 64;
    const int g    = lane >> 2;
    const int c    = lane & 3;

    const int i0 = blockIdx.y * 128;
    const int j0 = blockIdx.x * 128;
    const int nch = K >> 4;

    const int arow  = tid >> 1;
    const int acol8 = (tid & 1) * 8;
    const int gi_a  = i0 + arow;
    const bool aok  = gi_a < M;

    const int lm_row = ((lane >> 3) & 1) * 8 + (lane & 7);
    const int lm_col = ((lane >> 4) & 1) * 4;

    const float* BpT = Bp + (size_t)blockIdx.x * nch * 2048;

    auto load_stage = [&](int st, int ch) {
        const int k0 = ch * 16;
        float* asd = AsF + st * 2560 + arow * 20 + acol8;
        if (!aok) {
#pragma unroll
            for (int jj = 0; jj < 8; jj++) asd[jj] = 0.f;
        } else {
            const float* base;
            if (AMODE == 0) base = A + (size_t)gi_a * K + k0;
            else            base = (k0 < Hh) ? hbuf + (size_t)gi_a * Hh + k0
                                             : aggbuf + (size_t)gi_a * Hh + (k0 - Hh);
            uint32_t s = (uint32_t)__cvta_generic_to_shared(asd);
            cpa16(s, base + acol8);
            cpa16(s + 16, base + acol8 + 4);
        }
        const float* src = BpT + (size_t)ch * 2048 + tid * 4;
        uint32_t s = (uint32_t)__cvta_generic_to_shared(&BsF[st * 2048 + tid * 4]);
        cpa16(s, src);
        cpa16(s + 4096, src + 1024);
    };

    float acc[2][8][4];
#pragma unroll
    for (int a = 0; a < 2; a++)
#pragma unroll
        for (int b = 0; b < 8; b++)
#pragma unroll
            for (int q = 0; q < 4; q++) acc[a][b][q] = 0.f;

    // prologue: stages 0 and 1 in flight
    load_stage(0, 0);
    asm volatile("cp.async.commit_group;");
    if (nch > 1) {
        load_stage(1, 1);
        asm volatile("cp.async.commit_group;");
    }

    for (int ch = 0; ch < nch; ch++) {
        const int st = ch % 3;
        const bool more = (ch + 2 < nch);
        if (more) asm volatile("cp.async.wait_group 1;");
        else      asm volatile("cp.async.wait_group 0;");
        __syncthreads();
        // issue loads for chunk ch+2 into slot (ch+2)%3 == slot consumed at ch-1
        if (more) {
            load_stage((ch + 2) % 3, ch + 2);
            asm volatile("cp.async.commit_group;");
        }

#pragma unroll
        for (int ks = 0; ks < 2; ks++) {
            uint32_t af[2][4];
#pragma unroll
            for (int mf = 0; mf < 2; mf++) {
                uint32_t addr = (uint32_t)__cvta_generic_to_shared(
                    &AsF[st * 2560 + (wm + mf * 16 + lm_row) * 20 + ks * 8 + lm_col]);
                asm volatile(
                    "ldmatrix.sync.aligned.m8n8.x4.shared.b16 {%0,%1,%2,%3}, [%4];"
                    : "=r"(af[mf][0]), "=r"(af[mf][1]), "=r"(af[mf][2]), "=r"(af[mf][3])
                    : "r"(addr));
            }
#pragma unroll
            for (int nfp = 0; nfp < 4; nfp++) {
                float4 bv = *(const float4*)&BsF[st * 2048 +
                                                 ((ks * 8 + (wn >> 4) + nfp) * 32 + lane) * 4];
                uint32_t b0[2] = {__float_as_uint(bv.x), __float_as_uint(bv.y)};
                uint32_t b1[2] = {__float_as_uint(bv.z), __float_as_uint(bv.w)};
#pragma unroll
                for (int mf = 0; mf < 2; mf++) {
                    mma_tf32(acc[mf][2 * nfp + 0], af[mf], b0);
                    mma_tf32(acc[mf][2 * nfp + 1], af[mf], b1);
                }
            }
        }
    }

    if (EPI == 3) {
        float rsum[2][2] = {{0.f, 0.f}, {0.f, 0.f}};
#pragma unroll
        for (int mf = 0; mf < 2; mf++)
#pragma unroll
            for (int nf = 0; nf < 8; nf++)
#pragma unroll
                for (int rr = 0; rr < 2; rr++)
#pragma unroll
                    for (int q = 0; q < 2; q++) {
                        int oj = j0 + wn + nf * 8 + 2 * c + q;
                        float v = silu_f(acc[mf][nf][rr * 2 + q] + bias[oj]);
                        rsum[mf][rr] += v * wc2[oj];
                    }
#pragma unroll
        for (int mf = 0; mf < 2; mf++)
#pragma unroll
            for (int rr = 0; rr < 2; rr++) {
                float s = rsum[mf][rr];
                s += __shfl_xor_sync(0xffffffffu, s, 1);
                s += __shfl_xor_sync(0xffffffffu, s, 2);
                if (c == 0) {
                    int oi = i0 + wm + mf * 16 + g + rr * 8;
                    if (oi < M) atomicAdd(&cbuf[oi], s);
                }
            }
        return;
    }

#pragma unroll
    for (int mf = 0; mf < 2; mf++) {
#pragma unroll
        for (int rr = 0; rr < 2; rr++) {
            int oi = i0 + wm + mf * 16 + g + rr * 8;
            if (oi >= M) continue;
            int rE = 0;
            if (EPI == 4) rE = __ldg(&rowIdx[oi]);
#pragma unroll
            for (int nf = 0; nf < 8; nf++) {
                int oj0 = j0 + wn + nf * 8 + 2 * c;
                float vv[2];
#pragma unroll
                for (int q = 0; q < 2; q++) {
                    int oj = oj0 + q;
                    float v = acc[mf][nf][rr * 2 + q] + bias[oj];
                    if (EPI == 1 || EPI == 4) v = silu_f(v);
                    if (EPI == 2) v += C[(size_t)oi * Hh + oj];
                    if (RND) v = f2tf32_f(v);
                    C[(size_t)oi * Hh + oj] = v;
                    vv[q] = v;
                }
                if (EPI == 4) red_add_v2(&aggout[(size_t)rE * Hh + oj0], vv[0], vv[1]);
            }
        }
    }
}

// ---------------- edge combine ---------------------------------------------
#define EPB 32
__global__ __launch_bounds__(256, 4)
void edge_combine_kernel(const float* __restrict__ pre_r, const float* __restrict__ pre_c,
                         const float* __restrict__ radial, const float* __restrict__ eattr,
                         const int* __restrict__ row, const int* __restrict__ col,
                         const float* __restrict__ wrad,
                         const float* __restrict__ wea,
                         const float* __restrict__ bias,
                         float* __restrict__ m1)
{
    __shared__ float wrad_s[Hh];
    __shared__ float wea_s[EDd][Hh];
    __shared__ float b_s[Hh];
    __shared__ float ea_s[EPB][EDd];

    const int tid = threadIdx.x;
    const int e0  = blockIdx.x * EPB;

    wrad_s[tid] = wrad[tid];
    b_s[tid]    = bias[tid];
#pragma unroll
    for (int k = 0; k < EDd; k++) wea_s[k][tid] = wea[k * Hh + tid];
    for (int t = tid; t < EPB * EDd; t += 256) {
        int ee = t / EDd, kk = t % EDd;
        int e = e0 + ee;
        ea_s[ee][kk] = (e < Ee) ? eattr[e * EDd + kk] : 0.f;
    }
    __syncthreads();

    for (int ee = 0; ee < EPB; ee++) {
        int e = e0 + ee;
        if (e >= Ee) break;
        int r = __ldg(&row[e]);
        int c = __ldg(&col[e]);
        float rad = __ldg(&radial[e]);
        float acc = pre_r[(size_t)r * Hh + tid] + pre_c[(size_t)c * Hh + tid]
                  + rad * wrad_s[tid] + b_s[tid];
#pragma unroll
        for (int k = 0; k < EDd; k++) acc = fmaf(ea_s[ee][k], wea_s[k][tid], acc);
        m1[(size_t)e * Hh + tid] = f2tf32_f(silu_f(acc));
    }
}

// ---------------- SIMT SGEMM (small tails only) ----------------------------
template <int EPI>
__global__ void gemm_k(const float* __restrict__ A, const float* __restrict__ Bw,
                       const float* __restrict__ bias, float* __restrict__ C,
                       int M, int K, int Ncol)
{
    __shared__ float As[16][64];
    __shared__ float Bs[16][64];
    const int tid = threadIdx.x;
    const int tx = tid & 15, ty = tid >> 4;
    const int i0 = blockIdx.y * 64, j0 = blockIdx.x * 64;
    const int a_row = tid >> 2, a_k = (tid & 3) * 4;
    const int b_k = tid >> 4, b_j = (tid & 15) * 4;
    float acc[4][4] = {};
    const int gi = i0 + a_row;
    for (int k0 = 0; k0 < K; k0 += 16) {
#pragma unroll
        for (int q = 0; q < 4; q++) {
            int gk = k0 + a_k + q;
            As[a_k + q][a_row] = (gi < M && gk < K) ? A[(size_t)gi * K + gk] : 0.f;
        }
        int gk = k0 + b_k;
#pragma unroll
        for (int q = 0; q < 4; q++) {
            int gj = j0 + b_j + q;
            Bs[b_k][b_j + q] = (gk < K && gj < Ncol) ? Bw[(size_t)gk * Ncol + gj] : 0.f;
        }
        __syncthreads();
#pragma unroll
        for (int kk = 0; kk < 16; kk++) {
            float4 ra = *(const float4*)&As[kk][ty * 4];
            float4 rb = *(const float4*)&Bs[kk][tx * 4];
            float av[4] = {ra.x, ra.y, ra.z, ra.w};
            float bv[4] = {rb.x, rb.y, rb.z, rb.w};
#pragma unroll
            for (int m = 0; m < 4; m++)
#pragma unroll
                for (int n = 0; n < 4; n++) acc[m][n] += av[m] * bv[n];
        }
        __syncthreads();
    }
#pragma unroll
    for (int m = 0; m < 4; m++) {
        int oi = i0 + ty * 4 + m;
        if (oi >= M) continue;
#pragma unroll
        for (int n = 0; n < 4; n++) {
            int oj = j0 + tx * 4 + n;
            if (oj >= Ncol) continue;
            float v = acc[m][n] + bias[oj];
            if (EPI == 1) v = silu_f(v);
            if (EPI == 2) C[(size_t)oi * Ncol + oj] += v;
            else          C[(size_t)oi * Ncol + oj] = v;
        }
    }
}

// ---------------- small helper kernels -------------------------------------
__global__ void init_kernel(const float* __restrict__ pos, float* __restrict__ coord,
                            float* __restrict__ cnt)
{
    int i = blockIdx.x * blockDim.x + threadIdx.x;
    if (i >= Nn) return;
    cnt[i] = 0.f;
    coord[3 * i + 0] = pos[3 * i + 0];
    coord[3 * i + 1] = pos[3 * i + 1];
    coord[3 * i + 2] = pos[3 * i + 2];
}

__global__ void count_kernel(const int* __restrict__ row, float* __restrict__ cnt)
{
    int e = blockIdx.x * blockDim.x + threadIdx.x;
    if (e >= Ee) return;
    atomicAdd(&cnt[row[e]], 1.f);
}

__global__ void edge_geom_kernel(const float* __restrict__ coord,
                                 const int* __restrict__ row, const int* __restrict__ col,
                                 float* __restrict__ diff, float* __restrict__ radial)
{
    int e = blockIdx.x * blockDim.x + threadIdx.x;
    if (e >= Ee) return;
    int r = row[e], c = col[e];
    float dx = coord[3 * r + 0] - coord[3 * c + 0];
    float dy = coord[3 * r + 1] - coord[3 * c + 1];
    float dz = coord[3 * r + 2] - coord[3 * c + 2];
    diff[3 * e + 0] = dx; diff[3 * e + 1] = dy; diff[3 * e + 2] = dz;
    radial[e] = dx * dx + dy * dy + dz * dz;
}

// zero two buffers in one launch
__global__ void zero2_kernel(float* __restrict__ a, int na, float* __restrict__ b, int nb)
{
    int i = blockIdx.x * blockDim.x + threadIdx.x;
    if (i < na) a[i] = 0.f;
    else if (i < na + nb) b[i - na] = 0.f;
}

__global__ void coord_update_kernel(const float* __restrict__ diff, const float* __restrict__ cbuf,
                                    const int* __restrict__ row, const float* __restrict__ cnt,
                                    float* __restrict__ coord)
{
    int e = blockIdx.x * blockDim.x + threadIdx.x;
    if (e >= Ee) return;
    int r = row[e];
    float s = cbuf[e] / fmaxf(cnt[r], 1.f);
    atomicAdd(&coord[3 * r + 0], diff[3 * e + 0] * s);
    atomicAdd(&coord[3 * r + 1], diff[3 * e + 1] * s);
    atomicAdd(&coord[3 * r + 2], diff[3 * e + 2] * s);
}

__global__ void bounds_kernel(const int* __restrict__ batch, int* __restrict__ s,
                              int* __restrict__ e)
{
    int i = blockIdx.x * blockDim.x + threadIdx.x;
    if (i >= Nn) return;
    int b = batch[i];
    if (i == 0) s[b] = 0;
    else {
        int pb = batch[i - 1];
        if (pb != b) { s[b] = i; e[pb] = i; }
    }
    if (i == Nn - 1) e[b] = Nn;
}

__global__ void pool_kernel(const float* __restrict__ hout, const int* __restrict__ s,
                            const int* __restrict__ e, const float* __restrict__ frag,
                            const float* __restrict__ addf, float* __restrict__ z)
{
    int b = blockIdx.x;
    int j = threadIdx.x;
    float m = -INFINITY;
    int n0 = s[b], n1 = e[b];
    for (int n = n0; n < n1; n++) m = fmaxf(m, hout[(size_t)n * Hh + j]);
    z[b * ZD + j] = m;
    if (j < 8)       z[b * ZD + Hh + j] = frag[b * 8 + j];
    else if (j < 16) z[b * ZD + Hh + j] = addf[b * 8 + (j - 8)];
}

// ---------------- launch ----------------------------------------------------
extern "C" void kernel_launch(void* const* d_in, const int* in_sizes, int n_in,
                              void* d_out, int out_size)
{
    const float* x        = (const float*)d_in[0];
    const float* pos      = (const float*)d_in[1];
    const float* eattr    = (const float*)d_in[2];
    const float* frag     = (const float*)d_in[3];
    const float* addf     = (const float*)d_in[4];
    const int*   eidx     = (const int*)d_in[5];
    const int*   batch    = (const int*)d_in[6];
    const float* emb_in_w = (const float*)d_in[7];
    const float* emb_in_b = (const float*)d_in[8];
    const float* edge_w1  = (const float*)d_in[9];
    const float* edge_b1  = (const float*)d_in[10];
    const float* edge_w2  = (const float*)d_in[11];
    const float* edge_b2  = (const float*)d_in[12];
    const float* node_w1  = (const float*)d_in[13];
    const float* node_b1  = (const float*)d_in[14];
    const float* node_w2  = (const float*)d_in[15];
    const float* node_b2  = (const float*)d_in[16];
    const float* coord_w1 = (const float*)d_in[17];
    const float* coord_b1 = (const float*)d_in[18];
    const float* coord_w2 = (const float*)d_in[19];
    const float* emb_out_w= (const float*)d_in[20];
    const float* emb_out_b= (const float*)d_in[21];
    const float* res_w1   = (const float*)d_in[22];
    const float* res_b1   = (const float*)d_in[23];
    const float* res_w2   = (const float*)d_in[24];
    const float* res_b2   = (const float*)d_in[25];
    const float* head_w   = (const float*)d_in[26];
    const float* head_b   = (const float*)d_in[27];
    float* out = (float*)d_out;
    const int* row = eidx;
    const int* col = eidx + Ee;

    float *h, *hout, *n1, *agg, *coord, *cnt, *diff, *radial, *m1, *m2, *cbuf, *z, *tbuf;
    float *xr, *wr, *pr, *pc, *zb;
    int *sb, *eb;
    cudaGetSymbolAddress((void**)&h, g_h);
    cudaGetSymbolAddress((void**)&hout, g_hout);
    cudaGetSymbolAddress((void**)&n1, g_n1);
    cudaGetSymbolAddress((void**)&agg, g_agg);
    cudaGetSymbolAddress((void**)&coord, g_coord);
    cudaGetSymbolAddress((void**)&cnt, g_cnt);
    cudaGetSymbolAddress((void**)&diff, g_diff);
    cudaGetSymbolAddress((void**)&radial, g_radial);
    cudaGetSymbolAddress((void**)&m1, g_m1);
    cudaGetSymbolAddress((void**)&m2, g_m2);
    cudaGetSymbolAddress((void**)&cbuf, g_c);
    cudaGetSymbolAddress((void**)&z, g_z);
    cudaGetSymbolAddress((void**)&tbuf, g_t);
    cudaGetSymbolAddress((void**)&sb, g_s);
    cudaGetSymbolAddress((void**)&eb, g_e);
    cudaGetSymbolAddress((void**)&xr, g_xr);
    cudaGetSymbolAddress((void**)&wr, g_wr);
    cudaGetSymbolAddress((void**)&pr, g_pr);
    cudaGetSymbolAddress((void**)&pc, g_pc);
    cudaGetSymbolAddress((void**)&zb, g_zb);

    // opt-in dynamic smem for each gemm_tc instantiation
    cudaFuncSetAttribute(gemm_tc<0, 0, 1>, cudaFuncAttributeMaxDynamicSharedMemorySize, GT_SMEM_BYTES);
    cudaFuncSetAttribute(gemm_tc<0, 0, 0>, cudaFuncAttributeMaxDynamicSharedMemorySize, GT_SMEM_BYTES);
    cudaFuncSetAttribute(gemm_tc<0, 4, 1>, cudaFuncAttributeMaxDynamicSharedMemorySize, GT_SMEM_BYTES);
    cudaFuncSetAttribute(gemm_tc<0, 3, 0>, cudaFuncAttributeMaxDynamicSharedMemorySize, GT_SMEM_BYTES);
    cudaFuncSetAttribute(gemm_tc<2, 1, 1>, cudaFuncAttributeMaxDynamicSharedMemorySize, GT_SMEM_BYTES);
    cudaFuncSetAttribute(gemm_tc<0, 2, 1>, cudaFuncAttributeMaxDynamicSharedMemorySize, GT_SMEM_BYTES);

    const dim3 T(256), T256(256);
    const dim3 gE(2, Ee / 128);               // 2 x 2500
    const dim3 gN(2, (Nn + 127) / 128);       // 2 x 157

    // ---- pack weights into tf32 fragment order ----
    pack_w_kernel<<<dim3((SZ_K128 + 255) / 256, 1), T>>>(emb_in_w, wr + OFF_EMBW, 8, 3, 0, 0);
    pack_w_kernel<<<dim3((SZ_K256 + 255) / 256, Ll), T>>>(edge_w1, wr + OFF_PR, 16, 4,
                                                          (long)K1 * Hh, SZ_K256);
    pack_w_kernel<<<dim3((SZ_K256 + 255) / 256, Ll), T>>>(edge_w1 + (size_t)Hh * Hh, wr + OFF_PC, 16, 4,
                                                          (long)K1 * Hh, SZ_K256);
    pack_w_kernel<<<dim3((SZ_K256 + 255) / 256, Ll), T>>>(edge_w2, wr + OFF_EW2, 16, 4,
                                                          (long)Hh * Hh, SZ_K256);
    pack_w_kernel<<<dim3((SZ_K256 + 255) / 256, Ll), T>>>(coord_w1, wr + OFF_CW1, 16, 4,
                                                          (long)Hh * Hh, SZ_K256);
    pack_w_kernel<<<dim3((SZ_K512 + 255) / 256, Ll), T>>>(node_w1, wr + OFF_NW1, 32, 5,
                                                          (long)2 * Hh * Hh, SZ_K512);
    pack_w_kernel<<<dim3((SZ_K256 + 255) / 256, Ll), T>>>(node_w2, wr + OFF_NW2, 16, 4,
                                                          (long)Hh * Hh, SZ_K256);
    pack_w_kernel<<<dim3((SZ_K256 + 255) / 256, 1), T>>>(emb_out_w, wr + OFF_EOW, 16, 4, 0, 0);
    round_tf32_kernel<<<(Nn * Ff + 255) / 256, T>>>(x, xr, Nn * Ff);

    init_kernel<<<(Nn + 255) / 256, T>>>(pos, coord, cnt);
    count_kernel<<<(Ee + 255) / 256, T>>>(row, cnt);

    // h = x @ emb_in_w + b   (rounded)
    gemm_tc<0, 0, 1><<<gN, T256, GT_SMEM_BYTES>>>(xr, wr + OFF_EMBW, emb_in_b, h, Nn, Ff,
                                                  nullptr, nullptr, nullptr, nullptr, nullptr, nullptr);

    for (int l = 0; l < Ll; l++) {
        edge_geom_kernel<<<(Ee + 255) / 256, T>>>(coord, row, col, diff, radial);
        // node pre-projections (no bias; consumed in fp32)
        gemm_tc<0, 0, 0><<<gN, T256, GT_SMEM_BYTES>>>(h, wr + OFF_PR + (size_t)l * SZ_K256, zb, pr,
                                                      Nn, Hh, nullptr, nullptr, nullptr,
                                                      nullptr, nullptr, nullptr);
        gemm_tc<0, 0, 0><<<gN, T256, GT_SMEM_BYTES>>>(h, wr + OFF_PC + (size_t)l * SZ_K256, zb, pc,
                                                      Nn, Hh, nullptr, nullptr, nullptr,
                                                      nullptr, nullptr, nullptr);
        // m1 combine
        edge_combine_kernel<<<(Ee + EPB - 1) / EPB, T>>>(
            pr, pc, radial, eattr, row, col,
            edge_w1 + ((size_t)l * K1 + 2 * Hh) * Hh,
            edge_w1 + ((size_t)l * K1 + 2 * Hh + 1) * Hh,
            edge_b1 + l * Hh, m1);
        // zero agg + cbuf in one launch
        zero2_kernel<<<(Nn * Hh + Ee + 255) / 256, T>>>(agg, Nn * Hh, cbuf, Ee);
        // m2 = silu(m1 @ W2 + b2); fused agg scatter (red.v2)
        gemm_tc<0, 4, 1><<<gE, T256, GT_SMEM_BYTES>>>(m1, wr + OFF_EW2 + (size_t)l * SZ_K256,
                                                      edge_b2 + l * Hh, m2, Ee, Hh,
                                                      row, nullptr, nullptr,
                                                      nullptr, nullptr, agg);
        // c[e] = silu(m2 @ Wc1 + bc1) @ wc2
        gemm_tc<0, 3, 0><<<gE, T256, GT_SMEM_BYTES>>>(m2, wr + OFF_CW1 + (size_t)l * SZ_K256,
                                                      coord_b1 + l * Hh, nullptr, Ee, Hh,
                                                      nullptr, nullptr, nullptr,
                                                      coord_w2 + l * Hh, cbuf, nullptr);
        coord_update_kernel<<<(Ee + 255) / 256, T>>>(diff, cbuf, row, cnt, coord);
        round_inplace_kernel<<<(Nn * Hh + 255) / 256, T>>>(agg, Nn * Hh);
        // n1 = silu(concat(h,agg) @ nW1 + nb1)
        gemm_tc<2, 1, 1><<<gN, T256, GT_SMEM_BYTES>>>(nullptr, wr + OFF_NW1 + (size_t)l * SZ_K512,
                                                      node_b1 + l * Hh, n1, Nn, 2 * Hh,
                                                      nullptr, h, agg,
                                                      nullptr, nullptr, nullptr);
        // h += n1 @ nW2 + nb2
        gemm_tc<0, 2, 1><<<gN, T256, GT_SMEM_BYTES>>>(n1, wr + OFF_NW2 + (size_t)l * SZ_K256,
                                                      node_b2 + l * Hh, h, Nn, Hh,
                                                      nullptr, nullptr, nullptr,
                                                      nullptr, nullptr, nullptr);
    }

    // hout = h @ emb_out_w + b
    gemm_tc<0, 0, 0><<<gN, T256, GT_SMEM_BYTES>>>(h, wr + OFF_EOW, emb_out_b, hout, Nn, Hh,
                                                  nullptr, nullptr, nullptr,
                                                  nullptr, nullptr, nullptr);

    bounds_kernel<<<(Nn + 255) / 256, T>>>(batch, sb, eb);
    pool_kernel<<<Bb, T>>>(hout, sb, eb, frag, addf, z);

    gemm_k<1><<<dim3(4, 2), T>>>(z, res_w1, res_b1, tbuf, Bb, ZD, Hh);
    gemm_k<2><<<dim3((ZD + 63) / 64, 2), T>>>(tbuf, res_w2, res_b2, z, Bb, Hh, ZD);
    gemm_k<0><<<dim3((Pp + 63) / 64, 2), T>>>(z, head_w, head_b, out, Bb, ZD, Pp);
}

// round 15
// speedup vs baseline: 1.0903x; 1.0124x over previous
#include <cuda_runtime.h>
#include <math.h>
#include <stdint.h>

// Problem constants (fixed by the dataset)
#define Nn 20000
#define Ee 320000
#define Bb 128
#define Ff 128
#define Hh 256
#define EDd 16
#define Gg 16
#define Pp 2000
#define Ll 4
#define ZD (Hh + Gg)          // 272
#define K1 (2 * Hh + 1 + EDd) // 529

// ---------------- scratch (device globals; no allocation allowed) ----------
__device__ float g_h[Nn * Hh];
__device__ float g_hout[Nn * Hh];
__device__ float g_n1[Nn * Hh];
__device__ float g_agg[Nn * Hh];
__device__ float g_coord[Nn * 3];
__device__ float g_cnt[Nn];
__device__ float g_diff[Ee * 3];
__device__ float g_radial[Ee];
__device__ float g_m1[(size_t)Ee * Hh];
__device__ float g_m2[(size_t)Ee * Hh];
__device__ float g_c[Ee];
__device__ float g_z[Bb * ZD];
__device__ float g_t[Bb * Hh];
__device__ int   g_s[Bb];
__device__ int   g_e[Bb];
__device__ float g_xr[Nn * Ff];
__device__ float g_pp[(size_t)Nn * 512];  // fused [pre_r | pre_c] per node
__device__ float g_zb[512];               // zeros (zero-init)

// packed tf32 weights (fragment order), all Ncol=256 (PP interleaved per layer)
#define SZ_K128 (128 * 256)
#define SZ_K256 (256 * 256)
#define SZ_K512 (512 * 256)
#define OFF_EMBW 0
#define OFF_PP   (OFF_EMBW + SZ_K128)                 // Ll * 2 * SZ_K256 (PR|PC interleaved)
#define OFF_EW2  (OFF_PP + Ll * 2 * SZ_K256)
#define OFF_CW1  (OFF_EW2 + Ll * SZ_K256)
#define OFF_NW1  (OFF_CW1 + Ll * SZ_K256)
#define OFF_NW2  (OFF_NW1 + Ll * SZ_K512)
#define OFF_EOW  (OFF_NW2 + Ll * SZ_K256)
#define WR_TOTAL (OFF_EOW + SZ_K256)
__device__ float g_wr[WR_TOTAL];

// dynamic smem for gemm_tc (4-stage): As 4*128*20 + Bs 4*2048 floats
#define GT_NSTAGE 4
#define GT_AS_FLOATS (GT_NSTAGE * 128 * 20)
#define GT_SMEM_BYTES ((GT_AS_FLOATS + GT_NSTAGE * 2048) * 4)   // 73728 B

__device__ __forceinline__ float f2tf32_f(float x) {
    uint32_t r;
    asm("cvt.rna.tf32.f32 %0, %1;" : "=r"(r) : "f"(x));
    return __uint_as_float(r);
}

__device__ __forceinline__ void mma_tf32(float* d, const uint32_t* a, const uint32_t* b) {
    asm volatile(
        "mma.sync.aligned.m16n8k8.row.col.f32.tf32.tf32.f32 "
        "{%0,%1,%2,%3}, {%4,%5,%6,%7}, {%8,%9}, {%0,%1,%2,%3};"
        : "+f"(d[0]), "+f"(d[1]), "+f"(d[2]), "+f"(d[3])
        : "r"(a[0]), "r"(a[1]), "r"(a[2]), "r"(a[3]), "r"(b[0]), "r"(b[1]));
}

__device__ __forceinline__ void cpa16(uint32_t saddr, const void* gptr) {
    asm volatile("cp.async.cg.shared.global [%0], [%1], 16;" :: "r"(saddr), "l"(gptr));
}

// vectorized fire-and-forget reduction (sm_90+)
__device__ __forceinline__ void red_add_v2(float* gptr, float a, float b) {
    asm volatile("red.global.add.v2.f32 [%0], {%1, %2};"
                 :: "l"(gptr), "f"(a), "f"(b) : "memory");
}

__device__ __forceinline__ float silu_f(float v) { return v / (1.f + expf(-v)); }

__global__ void round_tf32_kernel(const float* __restrict__ in, float* __restrict__ out, int n)
{
    int i = blockIdx.x * blockDim.x + threadIdx.x;
    if (i < n) out[i] = f2tf32_f(in[i]);
}

__global__ void round_inplace_kernel(float* __restrict__ p, int n)
{
    int i = blockIdx.x * blockDim.x + threadIdx.x;
    if (i < n) p[i] = f2tf32_f(p[i]);
}

// pack W[K x 256] into fragment order [jt2][nch][ks2][nfp8][lane32][q4]
__global__ void pack_w_kernel(const float* __restrict__ src, float* __restrict__ dst,
                              int nch, int cb, long srcStride, long dstStride)
{
    int l = blockIdx.y;
    src += (size_t)l * srcStride;
    dst += (size_t)l * dstStride;
    int i = blockIdx.x * blockDim.x + threadIdx.x;
    int total = 2 * nch * 2048;
    if (i >= total) return;
    int q    = i & 3;
    int lane = (i >> 2) & 31;
    int nfp  = (i >> 7) & 7;
    int ks   = (i >> 10) & 1;
    int ch   = (i >> 11) & (nch - 1);
    int jt   = i >> (11 + cb);
    int n = jt * 128 + nfp * 16 + ((q >> 1) << 3) + (lane >> 2);
    int k = ch * 16 + ks * 8 + (lane & 3) + ((q & 1) << 2);
    dst[i] = f2tf32_f(src[(size_t)k * 256 + n]);
}

// ---------------- tf32 tensor-core GEMM: 256 thr, grid (NJT, M/128),
// 4-stage cp.async, ONE __syncthreads per K-chunk (CUTLASS multistage order).
// AMODE 0: A row-major ; 2: node concat [h | agg]
// EPI 0: C=v ; 1: C=silu(v) ; 2: C+=v
// EPI 3: no C write; cbuf[i] += sum_j silu(v_ij)*wc2[j]   (atomic)
// EPI 4: C=silu(v) AND agg[row[i]] += silu(v)             (red.v2)
// RND 1: round stored value to tf32.  ldC = C row stride.
template <int AMODE, int EPI, int RND>
__global__ __launch_bounds__(256, 2)
void gemm_tc(const float* __restrict__ A, const float* __restrict__ Bp,
             const float* __restrict__ bias, float* __restrict__ C,
             int M, int K, int ldC,
             const int* __restrict__ rowIdx,
             const float* __restrict__ hbuf, const float* __restrict__ aggbuf,
             const float* __restrict__ wc2, float* __restrict__ cbuf,
             float* __restrict__ aggout)
{
    extern __shared__ float smg[];
    float* AsF = smg;                       // [4][128][20]
    float* BsF = smg + GT_AS_FLOATS;        // [4][2048]

    const int tid  = threadIdx.x;
    const int lane = tid & 31;
    const int wid  = tid >> 5;
    const int wm   = (wid >> 1) * 32;
    const int wn   = (wid & 1) * 64;
    const int g    = lane >> 2;
    const int c    = lane & 3;

    const int i0 = blockIdx.y * 128;
    const int j0 = blockIdx.x * 128;
    const int nch = K >> 4;

    const int arow  = tid >> 1;
    const int acol8 = (tid & 1) * 8;
    const int gi_a  = i0 + arow;
    const bool aok  = gi_a < M;

    const int lm_row = ((lane >> 3) & 1) * 8 + (lane & 7);
    const int lm_col = ((lane >> 4) & 1) * 4;

    const float* BpT = Bp + (size_t)blockIdx.x * nch * 2048;

    auto load_stage = [&](int st, int ch) {
        const int k0 = ch * 16;
        float* asd = AsF + st * 2560 + arow * 20 + acol8;
        if (!aok) {
#pragma unroll
            for (int jj = 0; jj < 8; jj++) asd[jj] = 0.f;
        } else {
            const float* base;
            if (AMODE == 0) base = A + (size_t)gi_a * K + k0;
            else            base = (k0 < Hh) ? hbuf + (size_t)gi_a * Hh + k0
                                             : aggbuf + (size_t)gi_a * Hh + (k0 - Hh);
            uint32_t s = (uint32_t)__cvta_generic_to_shared(asd);
            cpa16(s, base + acol8);
            cpa16(s + 16, base + acol8 + 4);
        }
        const float* src = BpT + (size_t)ch * 2048 + tid * 4;
        uint32_t s = (uint32_t)__cvta_generic_to_shared(&BsF[st * 2048 + tid * 4]);
        cpa16(s, src);
        cpa16(s + 4096, src + 1024);
    };

    float acc[2][8][4];
#pragma unroll
    for (int a = 0; a < 2; a++)
#pragma unroll
        for (int b = 0; b < 8; b++)
#pragma unroll
            for (int q = 0; q < 4; q++) acc[a][b][q] = 0.f;

    // prologue: stages 0..2 in flight
    load_stage(0, 0);
    asm volatile("cp.async.commit_group;");
    if (nch > 1) { load_stage(1, 1); asm volatile("cp.async.commit_group;"); }
    if (nch > 2) { load_stage(2, 2); asm volatile("cp.async.commit_group;"); }

    for (int ch = 0; ch < nch; ch++) {
        const int st = ch % GT_NSTAGE;
        const int pending = nch - ch - 1;
        if (pending >= 2)      asm volatile("cp.async.wait_group 2;");
        else if (pending == 1) asm volatile("cp.async.wait_group 1;");
        else                   asm volatile("cp.async.wait_group 0;");
        __syncthreads();
        // issue loads for chunk ch+3 into slot (ch+3)%4 == slot consumed at ch-1
        if (ch + 3 < nch) {
            load_stage((ch + 3) % GT_NSTAGE, ch + 3);
            asm volatile("cp.async.commit_group;");
        }

#pragma unroll
        for (int ks = 0; ks < 2; ks++) {
            uint32_t af[2][4];
#pragma unroll
            for (int mf = 0; mf < 2; mf++) {
                uint32_t addr = (uint32_t)__cvta_generic_to_shared(
                    &AsF[st * 2560 + (wm + mf * 16 + lm_row) * 20 + ks * 8 + lm_col]);
                asm volatile(
                    "ldmatrix.sync.aligned.m8n8.x4.shared.b16 {%0,%1,%2,%3}, [%4];"
                    : "=r"(af[mf][0]), "=r"(af[mf][1]), "=r"(af[mf][2]), "=r"(af[mf][3])
                    : "r"(addr));
            }
#pragma unroll
            for (int nfp = 0; nfp < 4; nfp++) {
                float4 bv = *(const float4*)&BsF[st * 2048 +
                                                 ((ks * 8 + (wn >> 4) + nfp) * 32 + lane) * 4];
                uint32_t b0[2] = {__float_as_uint(bv.x), __float_as_uint(bv.y)};
                uint32_t b1[2] = {__float_as_uint(bv.z), __float_as_uint(bv.w)};
#pragma unroll
                for (int mf = 0; mf < 2; mf++) {
                    mma_tf32(acc[mf][2 * nfp + 0], af[mf], b0);
                    mma_tf32(acc[mf][2 * nfp + 1], af[mf], b1);
                }
            }
        }
    }

    if (EPI == 3) {
        float rsum[2][2] = {{0.f, 0.f}, {0.f, 0.f}};
#pragma unroll
        for (int mf = 0; mf < 2; mf++)
#pragma unroll
            for (int nf = 0; nf < 8; nf++)
#pragma unroll
                for (int rr = 0; rr < 2; rr++)
#pragma unroll
                    for (int q = 0; q < 2; q++) {
                        int oj = j0 + wn + nf * 8 + 2 * c + q;
                        float v = silu_f(acc[mf][nf][rr * 2 + q] + bias[oj]);
                        rsum[mf][rr] += v * wc2[oj];
                    }
#pragma unroll
        for (int mf = 0; mf < 2; mf++)
#pragma unroll
            for (int rr = 0; rr < 2; rr++) {
                float s = rsum[mf][rr];
                s += __shfl_xor_sync(0xffffffffu, s, 1);
                s += __shfl_xor_sync(0xffffffffu, s, 2);
                if (c == 0) {
                    int oi = i0 + wm + mf * 16 + g + rr * 8;
                    if (oi < M) atomicAdd(&cbuf[oi], s);
                }
            }
        return;
    }

#pragma unroll
    for (int mf = 0; mf < 2; mf++) {
#pragma unroll
        for (int rr = 0; rr < 2; rr++) {
            int oi = i0 + wm + mf * 16 + g + rr * 8;
            if (oi >= M) continue;
            int rE = 0;
            if (EPI == 4) rE = __ldg(&rowIdx[oi]);
#pragma unroll
            for (int nf = 0; nf < 8; nf++) {
                int oj0 = j0 + wn + nf * 8 + 2 * c;
                float vv[2];
#pragma unroll
                for (int q = 0; q < 2; q++) {
                    int oj = oj0 + q;
                    float v = acc[mf][nf][rr * 2 + q] + bias[oj];
                    if (EPI == 1 || EPI == 4) v = silu_f(v);
                    if (EPI == 2) v += C[(size_t)oi * ldC + oj];
                    if (RND) v = f2tf32_f(v);
                    C[(size_t)oi * ldC + oj] = v;
                    vv[q] = v;
                }
                if (EPI == 4) red_add_v2(&aggout[(size_t)rE * Hh + oj0], vv[0], vv[1]);
            }
        }
    }
}

// ---------------- edge combine (pp stride 512; unroll 2 for gather MLP) -----
#define EPB 32
__global__ __launch_bounds__(256, 4)
void edge_combine_kernel(const float* __restrict__ pp,
                         const float* __restrict__ radial, const float* __restrict__ eattr,
                         const int* __restrict__ row, const int* __restrict__ col,
                         const float* __restrict__ wrad,
                         const float* __restrict__ wea,
                         const float* __restrict__ bias,
                         float* __restrict__ m1)
{
    __shared__ float wrad_s[Hh];
    __shared__ float wea_s[EDd][Hh];
    __shared__ float b_s[Hh];
    __shared__ float ea_s[EPB][EDd];

    const int tid = threadIdx.x;
    const int e0  = blockIdx.x * EPB;

    wrad_s[tid] = wrad[tid];
    b_s[tid]    = bias[tid];
#pragma unroll
    for (int k = 0; k < EDd; k++) wea_s[k][tid] = wea[k * Hh + tid];
    for (int t = tid; t < EPB * EDd; t += 256) {
        int ee = t / EDd, kk = t % EDd;
        ea_s[ee][kk] = eattr[(e0 + ee) * EDd + kk];
    }
    __syncthreads();

#pragma unroll 2
    for (int ee = 0; ee < EPB; ee++) {
        int e = e0 + ee;
        int r = __ldg(&row[e]);
        int c = __ldg(&col[e]);
        float rad = __ldg(&radial[e]);
        float acc = pp[(size_t)r * 512 + tid] + pp[(size_t)c * 512 + 256 + tid]
                  + rad * wrad_s[tid] + b_s[tid];
#pragma unroll
        for (int k = 0; k < EDd; k++) acc = fmaf(ea_s[ee][k], wea_s[k][tid], acc);
        m1[(size_t)e * Hh + tid] = f2tf32_f(silu_f(acc));
    }
}

// ---------------- SIMT SGEMM (small tails only) ----------------------------
template <int EPI>
__global__ void gemm_k(const float* __restrict__ A, const float* __restrict__ Bw,
                       const float* __restrict__ bias, float* __restrict__ C,
                       int M, int K, int Ncol)
{
    __shared__ float As[16][64];
    __shared__ float Bs[16][64];
    const int tid = threadIdx.x;
    const int tx = tid & 15, ty = tid >> 4;
    const int i0 = blockIdx.y * 64, j0 = blockIdx.x * 64;
    const int a_row = tid >> 2, a_k = (tid & 3) * 4;
    const int b_k = tid >> 4, b_j = (tid & 15) * 4;
    float acc[4][4] = {};
    const int gi = i0 + a_row;
    for (int k0 = 0; k0 < K; k0 += 16) {
#pragma unroll
        for (int q = 0; q < 4; q++) {
            int gk = k0 + a_k + q;
            As[a_k + q][a_row] = (gi < M && gk < K) ? A[(size_t)gi * K + gk] : 0.f;
        }
        int gk = k0 + b_k;
#pragma unroll
        for (int q = 0; q < 4; q++) {
            int gj = j0 + b_j + q;
            Bs[b_k][b_j + q] = (gk < K && gj < Ncol) ? Bw[(size_t)gk * Ncol + gj] : 0.f;
        }
        __syncthreads();
#pragma unroll
        for (int kk = 0; kk < 16; kk++) {
            float4 ra = *(const float4*)&As[kk][ty * 4];
            float4 rb = *(const float4*)&Bs[kk][tx * 4];
            float av[4] = {ra.x, ra.y, ra.z, ra.w};
            float bv[4] = {rb.x, rb.y, rb.z, rb.w};
#pragma unroll
            for (int m = 0; m < 4; m++)
#pragma unroll
                for (int n = 0; n < 4; n++) acc[m][n] += av[m] * bv[n];
        }
        __syncthreads();
    }
#pragma unroll
    for (int m = 0; m < 4; m++) {
        int oi = i0 + ty * 4 + m;
        if (oi >= M) continue;
#pragma unroll
        for (int n = 0; n < 4; n++) {
            int oj = j0 + tx * 4 + n;
            if (oj >= Ncol) continue;
            float v = acc[m][n] + bias[oj];
            if (EPI == 1) v = silu_f(v);
            if (EPI == 2) C[(size_t)oi * Ncol + oj] += v;
            else          C[(size_t)oi * Ncol + oj] = v;
        }
    }
}

// ---------------- small helper kernels -------------------------------------
__global__ void init_kernel(const float* __restrict__ pos, float* __restrict__ coord,
                            float* __restrict__ cnt)
{
    int i = blockIdx.x * blockDim.x + threadIdx.x;
    if (i >= Nn) return;
    cnt[i] = 0.f;
    coord[3 * i + 0] = pos[3 * i + 0];
    coord[3 * i + 1] = pos[3 * i + 1];
    coord[3 * i + 2] = pos[3 * i + 2];
}

__global__ void count_kernel(const int* __restrict__ row, float* __restrict__ cnt)
{
    int e = blockIdx.x * blockDim.x + threadIdx.x;
    if (e >= Ee) return;
    atomicAdd(&cnt[row[e]], 1.f);
}

__global__ void edge_geom_kernel(const float* __restrict__ coord,
                                 const int* __restrict__ row, const int* __restrict__ col,
                                 float* __restrict__ diff, float* __restrict__ radial)
{
    int e = blockIdx.x * blockDim.x + threadIdx.x;
    if (e >= Ee) return;
    int r = row[e], c = col[e];
    float dx = coord[3 * r + 0] - coord[3 * c + 0];
    float dy = coord[3 * r + 1] - coord[3 * c + 1];
    float dz = coord[3 * r + 2] - coord[3 * c + 2];
    diff[3 * e + 0] = dx; diff[3 * e + 1] = dy; diff[3 * e + 2] = dz;
    radial[e] = dx * dx + dy * dy + dz * dz;
}

// zero two buffers in one launch
__global__ void zero2_kernel(float* __restrict__ a, int na, float* __restrict__ b, int nb)
{
    int i = blockIdx.x * blockDim.x + threadIdx.x;
    if (i < na) a[i] = 0.f;
    else if (i < na + nb) b[i - na] = 0.f;
}

__global__ void coord_update_kernel(const float* __restrict__ diff, const float* __restrict__ cbuf,
                                    const int* __restrict__ row, const float* __restrict__ cnt,
                                    float* __restrict__ coord)
{
    int e = blockIdx.x * blockDim.x + threadIdx.x;
    if (e >= Ee) return;
    int r = row[e];
    float s = cbuf[e] / fmaxf(cnt[r], 1.f);
    atomicAdd(&coord[3 * r + 0], diff[3 * e + 0] * s);
    atomicAdd(&coord[3 * r + 1], diff[3 * e + 1] * s);
    atomicAdd(&coord[3 * r + 2], diff[3 * e + 2] * s);
}

__global__ void bounds_kernel(const int* __restrict__ batch, int* __restrict__ s,
                              int* __restrict__ e)
{
    int i = blockIdx.x * blockDim.x + threadIdx.x;
    if (i >= Nn) return;
    int b = batch[i];
    if (i == 0) s[b] = 0;
    else {
        int pb = batch[i - 1];
        if (pb != b) { s[b] = i; e[pb] = i; }
    }
    if (i == Nn - 1) e[b] = Nn;
}

__global__ void pool_kernel(const float* __restrict__ hout, const int* __restrict__ s,
                            const int* __restrict__ e, const float* __restrict__ frag,
                            const float* __restrict__ addf, float* __restrict__ z)
{
    int b = blockIdx.x;
    int j = threadIdx.x;
    float m = -INFINITY;
    int n0 = s[b], n1 = e[b];
    for (int n = n0; n < n1; n++) m = fmaxf(m, hout[(size_t)n * Hh + j]);
    z[b * ZD + j] = m;
    if (j < 8)       z[b * ZD + Hh + j] = frag[b * 8 + j];
    else if (j < 16) z[b * ZD + Hh + j] = addf[b * 8 + (j - 8)];
}

// ---------------- launch ----------------------------------------------------
extern "C" void kernel_launch(void* const* d_in, const int* in_sizes, int n_in,
                              void* d_out, int out_size)
{
    const float* x        = (const float*)d_in[0];
    const float* pos      = (const float*)d_in[1];
    const float* eattr    = (const float*)d_in[2];
    const float* frag     = (const float*)d_in[3];
    const float* addf     = (const float*)d_in[4];
    const int*   eidx     = (const int*)d_in[5];
    const int*   batch    = (const int*)d_in[6];
    const float* emb_in_w = (const float*)d_in[7];
    const float* emb_in_b = (const float*)d_in[8];
    const float* edge_w1  = (const float*)d_in[9];
    const float* edge_b1  = (const float*)d_in[10];
    const float* edge_w2  = (const float*)d_in[11];
    const float* edge_b2  = (const float*)d_in[12];
    const float* node_w1  = (const float*)d_in[13];
    const float* node_b1  = (const float*)d_in[14];
    const float* node_w2  = (const float*)d_in[15];
    const float* node_b2  = (const float*)d_in[16];
    const float* coord_w1 = (const float*)d_in[17];
    const float* coord_b1 = (const float*)d_in[18];
    const float* coord_w2 = (const float*)d_in[19];
    const float* emb_out_w= (const float*)d_in[20];
    const float* emb_out_b= (const float*)d_in[21];
    const float* res_w1   = (const float*)d_in[22];
    const float* res_b1   = (const float*)d_in[23];
    const float* res_w2   = (const float*)d_in[24];
    const float* res_b2   = (const float*)d_in[25];
    const float* head_w   = (const float*)d_in[26];
    const float* head_b   = (const float*)d_in[27];
    float* out = (float*)d_out;
    const int* row = eidx;
    const int* col = eidx + Ee;

    float *h, *hout, *n1, *agg, *coord, *cnt, *diff, *radial, *m1, *m2, *cbuf, *z, *tbuf;
    float *xr, *wr, *pp, *zb;
    int *sb, *eb;
    cudaGetSymbolAddress((void**)&h, g_h);
    cudaGetSymbolAddress((void**)&hout, g_hout);
    cudaGetSymbolAddress((void**)&n1, g_n1);
    cudaGetSymbolAddress((void**)&agg, g_agg);
    cudaGetSymbolAddress((void**)&coord, g_coord);
    cudaGetSymbolAddress((void**)&cnt, g_cnt);
    cudaGetSymbolAddress((void**)&diff, g_diff);
    cudaGetSymbolAddress((void**)&radial, g_radial);
    cudaGetSymbolAddress((void**)&m1, g_m1);
    cudaGetSymbolAddress((void**)&m2, g_m2);
    cudaGetSymbolAddress((void**)&cbuf, g_c);
    cudaGetSymbolAddress((void**)&z, g_z);
    cudaGetSymbolAddress((void**)&tbuf, g_t);
    cudaGetSymbolAddress((void**)&sb, g_s);
    cudaGetSymbolAddress((void**)&eb, g_e);
    cudaGetSymbolAddress((void**)&xr, g_xr);
    cudaGetSymbolAddress((void**)&wr, g_wr);
    cudaGetSymbolAddress((void**)&pp, g_pp);
    cudaGetSymbolAddress((void**)&zb, g_zb);

    // opt-in dynamic smem for each gemm_tc instantiation
    cudaFuncSetAttribute(gemm_tc<0, 0, 1>, cudaFuncAttributeMaxDynamicSharedMemorySize, GT_SMEM_BYTES);
    cudaFuncSetAttribute(gemm_tc<0, 0, 0>, cudaFuncAttributeMaxDynamicSharedMemorySize, GT_SMEM_BYTES);
    cudaFuncSetAttribute(gemm_tc<0, 4, 1>, cudaFuncAttributeMaxDynamicSharedMemorySize, GT_SMEM_BYTES);
    cudaFuncSetAttribute(gemm_tc<0, 3, 0>, cudaFuncAttributeMaxDynamicSharedMemorySize, GT_SMEM_BYTES);
    cudaFuncSetAttribute(gemm_tc<2, 1, 1>, cudaFuncAttributeMaxDynamicSharedMemorySize, GT_SMEM_BYTES);
    cudaFuncSetAttribute(gemm_tc<0, 2, 1>, cudaFuncAttributeMaxDynamicSharedMemorySize, GT_SMEM_BYTES);

    const dim3 T(256), T256(256);
    const dim3 gE(2, Ee / 128);               // 2 x 2500
    const dim3 gN(2, (Nn + 127) / 128);       // 2 x 157
    const dim3 gPP(4, (Nn + 127) / 128);      // 4 x 157 (merged pr|pc, N=512)

    // ---- pack weights into tf32 fragment order ----
    pack_w_kernel<<<dim3((SZ_K128 + 255) / 256, 1), T>>>(emb_in_w, wr + OFF_EMBW, 8, 3, 0, 0);
    // PR|PC interleaved per layer: layer stride 2*SZ_K256
    pack_w_kernel<<<dim3((SZ_K256 + 255) / 256, Ll), T>>>(edge_w1, wr + OFF_PP, 16, 4,
                                                          (long)K1 * Hh, 2L * SZ_K256);
    pack_w_kernel<<<dim3((SZ_K256 + 255) / 256, Ll), T>>>(edge_w1 + (size_t)Hh * Hh,
                                                          wr + OFF_PP + SZ_K256, 16, 4,
                                                          (long)K1 * Hh, 2L * SZ_K256);
    pack_w_kernel<<<dim3((SZ_K256 + 255) / 256, Ll), T>>>(edge_w2, wr + OFF_EW2, 16, 4,
                                                          (long)Hh * Hh, SZ_K256);
    pack_w_kernel<<<dim3((SZ_K256 + 255) / 256, Ll), T>>>(coord_w1, wr + OFF_CW1, 16, 4,
                                                          (long)Hh * Hh, SZ_K256);
    pack_w_kernel<<<dim3((SZ_K512 + 255) / 256, Ll), T>>>(node_w1, wr + OFF_NW1, 32, 5,
                                                          (long)2 * Hh * Hh, SZ_K512);
    pack_w_kernel<<<dim3((SZ_K256 + 255) / 256, Ll), T>>>(node_w2, wr + OFF_NW2, 16, 4,
                                                          (long)Hh * Hh, SZ_K256);
    pack_w_kernel<<<dim3((SZ_K256 + 255) / 256, 1), T>>>(emb_out_w, wr + OFF_EOW, 16, 4, 0, 0);
    round_tf32_kernel<<<(Nn * Ff + 255) / 256, T>>>(x, xr, Nn * Ff);

    init_kernel<<<(Nn + 255) / 256, T>>>(pos, coord, cnt);
    count_kernel<<<(Ee + 255) / 256, T>>>(row, cnt);

    // h = x @ emb_in_w + b   (rounded)
    gemm_tc<0, 0, 1><<<gN, T256, GT_SMEM_BYTES>>>(xr, wr + OFF_EMBW, emb_in_b, h, Nn, Ff, Hh,
                                                  nullptr, nullptr, nullptr, nullptr, nullptr, nullptr);

    for (int l = 0; l < Ll; l++) {
        edge_geom_kernel<<<(Ee + 255) / 256, T>>>(coord, row, col, diff, radial);
        // merged node pre-projections: pp[:,0:256]=h@W1top, pp[:,256:512]=h@W1bot
        gemm_tc<0, 0, 0><<<gPP, T256, GT_SMEM_BYTES>>>(h, wr + OFF_PP + (size_t)l * 2 * SZ_K256,
                                                       zb, pp, Nn, Hh, 512,
                                                       nullptr, nullptr, nullptr,
                                                       nullptr, nullptr, nullptr);
        // m1 combine
        edge_combine_kernel<<<Ee / EPB, T>>>(
            pp, radial, eattr, row, col,
            edge_w1 + ((size_t)l * K1 + 2 * Hh) * Hh,
            edge_w1 + ((size_t)l * K1 + 2 * Hh + 1) * Hh,
            edge_b1 + l * Hh, m1);
        // zero agg + cbuf in one launch
        zero2_kernel<<<(Nn * Hh + Ee + 255) / 256, T>>>(agg, Nn * Hh, cbuf, Ee);
        // m2 = silu(m1 @ W2 + b2); fused agg scatter (red.v2)
        gemm_tc<0, 4, 1><<<gE, T256, GT_SMEM_BYTES>>>(m1, wr + OFF_EW2 + (size_t)l * SZ_K256,
                                                      edge_b2 + l * Hh, m2, Ee, Hh, Hh,
                                                      row, nullptr, nullptr,
                                                      nullptr, nullptr, agg);
        // c[e] = silu(m2 @ Wc1 + bc1) @ wc2
        gemm_tc<0, 3, 0><<<gE, T256, GT_SMEM_BYTES>>>(m2, wr + OFF_CW1 + (size_t)l * SZ_K256,
                                                      coord_b1 + l * Hh, nullptr, Ee, Hh, Hh,
                                                      nullptr, nullptr, nullptr,
                                                      coord_w2 + l * Hh, cbuf, nullptr);
        coord_update_kernel<<<(Ee + 255) / 256, T>>>(diff, cbuf, row, cnt, coord);
        round_inplace_kernel<<<(Nn * Hh + 255) / 256, T>>>(agg, Nn * Hh);
        // n1 = silu(concat(h,agg) @ nW1 + nb1)
        gemm_tc<2, 1, 1><<<gN, T256, GT_SMEM_BYTES>>>(nullptr, wr + OFF_NW1 + (size_t)l * SZ_K512,
                                                      node_b1 + l * Hh, n1, Nn, 2 * Hh, Hh,
                                                      nullptr, h, agg,
                                                      nullptr, nullptr, nullptr);
        // h += n1 @ nW2 + nb2
        gemm_tc<0, 2, 1><<<gN, T256, GT_SMEM_BYTES>>>(n1, wr + OFF_NW2 + (size_t)l * SZ_K256,
                                                      node_b2 + l * Hh, h, Nn, Hh, Hh,
                                                      nullptr, nullptr, nullptr,
                                                      nullptr, nullptr, nullptr);
    }

    // hout = h @ emb_out_w + b
    gemm_tc<0, 0, 0><<<gN, T256, GT_SMEM_BYTES>>>(h, wr + OFF_EOW, emb_out_b, hout, Nn, Hh, Hh,
                                                  nullptr, nullptr, nullptr,
                                                  nullptr, nullptr, nullptr);

    bounds_kernel<<<(Nn + 255) / 256, T>>>(batch, sb, eb);
    pool_kernel<<<Bb, T>>>(hout, sb, eb, frag, addf, z);

    gemm_k<1><<<dim3(4, 2), T>>>(z, res_w1, res_b1, tbuf, Bb, ZD, Hh);
    gemm_k<2><<<dim3((ZD + 63) / 64, 2), T>>>(tbuf, res_w2, res_b2, z, Bb, Hh, ZD);
    gemm_k<0><<<dim3((Pp + 63) / 64, 2), T>>>(z, head_w, head_b, out, Bb, ZD, Pp);
}